// round 1
// baseline (speedup 1.0000x reference)
#include <cuda_runtime.h>

#define Bn 64
#define Tn 2048
#define In 128
#define Hn 256
#define NPAIR 2                 // output column-pairs per CTA
#define GCTA  (Hn / NPAIR)      // 128 CTAs
#define THREADS 128

typedef unsigned long long u64;

// ---------------- device state (scratch; no allocations allowed) ----------------
__device__ float g_h0[2][Bn][Hn];
__device__ float g_h1[2][Bn][Hn];
__device__ unsigned g_count;

// ---------------- helpers ----------------
__device__ __forceinline__ void fma2(u64 &d, const u64 a, const u64 b) {
    // packed fp32x2 FMA (SASS FFMA2) — PTX-only form on sm_103a
    asm("fma.rn.f32x2 %0, %1, %2, %0;" : "+l"(d) : "l"(a), "l"(b));
}

__device__ __forceinline__ float sum2(u64 v) {
    float lo = __uint_as_float((unsigned)(v & 0xffffffffull));
    float hi = __uint_as_float((unsigned)(v >> 32));
    return lo + hi;
}

__device__ __forceinline__ float sigmoidf_(float v) {
    return 1.0f / (1.0f + __expf(-v));
}

// Accumulate over a K-segment: two input rows (global), two weight columns (smem),
// packed even/odd accumulation in f32x2.
template<int KL>
__device__ __forceinline__ void accum_seg(
    const float* __restrict__ in0, const float* __restrict__ in1,
    const float* __restrict__ wc,  const float* __restrict__ wa,
    u64 &c0, u64 &a0, u64 &c1, u64 &a1)
{
    const ulonglong2* p0 = (const ulonglong2*)in0;
    const ulonglong2* p1 = (const ulonglong2*)in1;
    const ulonglong2* pc = (const ulonglong2*)wc;
    const ulonglong2* pa = (const ulonglong2*)wa;
#pragma unroll 8
    for (int i = 0; i < KL / 4; i++) {
        ulonglong2 v0 = p0[i];
        ulonglong2 v1 = p1[i];
        ulonglong2 wcv = pc[i];
        ulonglong2 wav = pa[i];
        fma2(c0, v0.x, wcv.x); fma2(c0, v0.y, wcv.y);
        fma2(a0, v0.x, wav.x); fma2(a0, v0.y, wav.y);
        fma2(c1, v1.x, wcv.x); fma2(c1, v1.y, wcv.y);
        fma2(a1, v1.x, wav.x); fma2(a1, v1.y, wav.y);
    }
}

// Software grid barrier: monotonic counter, release (fence+atomic) / acquire (poll+fence).
__device__ __forceinline__ void grid_barrier(unsigned target) {
    __syncthreads();
    if (threadIdx.x == 0) {
        __threadfence();
        atomicAdd(&g_count, 1u);
        while (*((volatile unsigned*)&g_count) < target) { }
        __threadfence();
    }
    __syncthreads();
}

// ---------------- init: reset barrier + zero hidden state (runs every replay) ----------------
__global__ void init_kernel() {
    int i = blockIdx.x * blockDim.x + threadIdx.x;
    if (i == 0) g_count = 0u;
    float* h0 = &g_h0[0][0][0];
    float* h1 = &g_h1[0][0][0];
    const int n = 2 * Bn * Hn;
    for (int j = i; j < n; j += gridDim.x * blockDim.x) {
        h0[j] = 0.0f;
        h1[j] = 0.0f;
    }
}

// ---------------- persistent recurrent kernel ----------------
__global__ void __launch_bounds__(THREADS, 1) rnn_persistent(
    const float* __restrict__ x,
    const float* __restrict__ Wih0, const float* __restrict__ Whh0, const float* __restrict__ bh0,
    const float* __restrict__ Wax0, const float* __restrict__ Wah0, const float* __restrict__ ba0,
    const float* __restrict__ Wih1, const float* __restrict__ Whh1, const float* __restrict__ bh1,
    const float* __restrict__ Wax1, const float* __restrict__ Wah1, const float* __restrict__ ba1,
    float* __restrict__ out)
{
    // Weight columns (column-major over K) for this CTA's NPAIR output columns.
    // Layer 0 fused K = 384:  k<128 -> x-proj (Wih0/Wax0), k>=128 -> h0-proj (Whh0/Wah0)
    // Layer 1 fused K = 512:  k<256 -> cur-proj (Wih1/Wax1), k>=256 -> h1-proj (Whh1/Wah1)
    __shared__ float wAc[NPAIR][384];
    __shared__ float wAa[NPAIR][384];
    __shared__ float wBc[NPAIR][512];
    __shared__ float wBa[NPAIR][512];
    __shared__ float red[64][4];
    __shared__ float biasv[4][NPAIR];

    const int tid  = threadIdx.x;
    const int cta  = blockIdx.x;
    const int col0 = cta * NPAIR;

    // gather weights into smem (one-time)
    for (int idx = tid; idx < NPAIR * 384; idx += THREADS) {
        int p = idx / 384, k = idx % 384;
        int col = col0 + p;
        wAc[p][k] = (k < In) ? Wih0[k * Hn + col] : Whh0[(k - In) * Hn + col];
        wAa[p][k] = (k < In) ? Wax0[k * Hn + col] : Wah0[(k - In) * Hn + col];
    }
    for (int idx = tid; idx < NPAIR * 512; idx += THREADS) {
        int p = idx / 512, k = idx % 512;
        int col = col0 + p;
        wBc[p][k] = (k < Hn) ? Wih1[k * Hn + col] : Whh1[(k - Hn) * Hn + col];
        wBa[p][k] = (k < Hn) ? Wax1[k * Hn + col] : Wah1[(k - Hn) * Hn + col];
    }
    if (tid < NPAIR) {
        int col = col0 + tid;
        biasv[0][tid] = bh0[col];
        biasv[1][tid] = ba0[col];
        biasv[2][tid] = bh1[col];
        biasv[3][tid] = ba1[col];
    }
    __syncthreads();

    // thread decomposition: ks = K-split half, slot -> (rowgroup, pair)
    const int ks   = tid >> 6;        // 0 or 1
    const int slot = tid & 63;        // 0..63
    const int p    = slot & (NPAIR - 1);
    const int rg   = slot >> 1;       // 0..31
    const int r0   = rg * 2;
    const int r1   = r0 + 1;
    const int col  = col0 + p;

    // ---- layer 0 at step s: h0_new = a*tanh(cand) + (1-a)*h0 ----
    auto phaseA = [&](int s) {
        const float* h0prev = &g_h0[(s + 1) & 1][0][0];
        float*       h0next = &g_h0[s & 1][0][0];
        u64 c0 = 0, a0 = 0, c1 = 0, a1 = 0;
        if (ks == 0) {
            accum_seg<128>(x + (r0 * Tn + s) * In, x + (r1 * Tn + s) * In,
                           wAc[p], wAa[p], c0, a0, c1, a1);
            accum_seg<64>(h0prev + r0 * Hn, h0prev + r1 * Hn,
                          wAc[p] + 128, wAa[p] + 128, c0, a0, c1, a1);
        } else {
            accum_seg<192>(h0prev + r0 * Hn + 64, h0prev + r1 * Hn + 64,
                           wAc[p] + 192, wAa[p] + 192, c0, a0, c1, a1);
        }
        __syncthreads();
        if (ks == 1) {
            red[slot][0] = sum2(c0); red[slot][1] = sum2(a0);
            red[slot][2] = sum2(c1); red[slot][3] = sum2(a1);
        }
        __syncthreads();
        if (ks == 0) {
            float cc0 = sum2(c0) + red[slot][0] + biasv[0][p];
            float aa0 = sum2(a0) + red[slot][1] + biasv[1][p];
            float cc1 = sum2(c1) + red[slot][2] + biasv[0][p];
            float aa1 = sum2(a1) + red[slot][3] + biasv[1][p];
            float al0 = sigmoidf_(aa0), al1 = sigmoidf_(aa1);
            float t0 = tanhf(cc0),      t1 = tanhf(cc1);
            float hp0 = h0prev[r0 * Hn + col];
            float hp1 = h0prev[r1 * Hn + col];
            h0next[r0 * Hn + col] = al0 * t0 + (1.0f - al0) * hp0;
            h0next[r1 * Hn + col] = al1 * t1 + (1.0f - al1) * hp1;
        }
    };

    // ---- layer 1 at step t: writes h1 state and the [B,T,H] output ----
    auto phaseB = [&](int t) {
        const float* cur    = &g_h0[t & 1][0][0];
        const float* h1prev = &g_h1[(t + 1) & 1][0][0];
        float*       h1next = &g_h1[t & 1][0][0];
        u64 c0 = 0, a0 = 0, c1 = 0, a1 = 0;
        if (ks == 0) {
            accum_seg<256>(cur + r0 * Hn, cur + r1 * Hn,
                           wBc[p], wBa[p], c0, a0, c1, a1);
        } else {
            accum_seg<256>(h1prev + r0 * Hn, h1prev + r1 * Hn,
                           wBc[p] + 256, wBa[p] + 256, c0, a0, c1, a1);
        }
        __syncthreads();
        if (ks == 1) {
            red[slot][0] = sum2(c0); red[slot][1] = sum2(a0);
            red[slot][2] = sum2(c1); red[slot][3] = sum2(a1);
        }
        __syncthreads();
        if (ks == 0) {
            float cc0 = sum2(c0) + red[slot][0] + biasv[2][p];
            float aa0 = sum2(a0) + red[slot][1] + biasv[3][p];
            float cc1 = sum2(c1) + red[slot][2] + biasv[2][p];
            float aa1 = sum2(a1) + red[slot][3] + biasv[3][p];
            float al0 = sigmoidf_(aa0), al1 = sigmoidf_(aa1);
            float t0 = tanhf(cc0),      t1 = tanhf(cc1);
            float hp0 = h1prev[r0 * Hn + col];
            float hp1 = h1prev[r1 * Hn + col];
            float hn0 = al0 * t0 + (1.0f - al0) * hp0;
            float hn1 = al1 * t1 + (1.0f - al1) * hp1;
            h1next[r0 * Hn + col] = hn0;
            h1next[r1 * Hn + col] = hn1;
            out[(r0 * Tn + t) * Hn + col] = hn0;
            out[(r1 * Tn + t) * Hn + col] = hn1;
        }
    };

    // ---- main sequential loop: one grid barrier per timestep ----
    phaseA(0);
    unsigned bar = 1;
    grid_barrier(GCTA * bar); bar++;
    for (int t = 0; t < Tn; t++) {
        phaseB(t);
        if (t < Tn - 1) phaseA(t + 1);
        grid_barrier(GCTA * bar); bar++;
    }

    // ---- h_final: [L=2][B][H] appended after outputs ----
    float* hf = out + (size_t)Bn * Tn * Hn;
    const float* h0f = &g_h0[(Tn - 1) & 1][0][0];
    const float* h1f = &g_h1[(Tn - 1) & 1][0][0];
    for (int idx = tid; idx < Bn * NPAIR; idx += THREADS) {
        int r = idx / NPAIR;
        int pp = idx % NPAIR;
        int c = col0 + pp;
        hf[r * Hn + c]           = h0f[r * Hn + c];
        hf[Bn * Hn + r * Hn + c] = h1f[r * Hn + c];
    }
}

// ---------------- launch ----------------
extern "C" void kernel_launch(void* const* d_in, const int* in_sizes, int n_in,
                              void* d_out, int out_size) {
    const float* x    = (const float*)d_in[0];
    const float* Wih0 = (const float*)d_in[1];
    const float* Whh0 = (const float*)d_in[2];
    const float* bh0  = (const float*)d_in[3];
    const float* Wax0 = (const float*)d_in[4];
    const float* Wah0 = (const float*)d_in[5];
    const float* ba0  = (const float*)d_in[6];
    const float* Wih1 = (const float*)d_in[7];
    const float* Whh1 = (const float*)d_in[8];
    const float* bh1  = (const float*)d_in[9];
    const float* Wax1 = (const float*)d_in[10];
    const float* Wah1 = (const float*)d_in[11];
    const float* ba1  = (const float*)d_in[12];
    float* out = (float*)d_out;

    init_kernel<<<64, 256>>>();
    rnn_persistent<<<GCTA, THREADS>>>(x,
        Wih0, Whh0, bh0, Wax0, Wah0, ba0,
        Wih1, Whh1, bh1, Wax1, Wah1, ba1,
        out);
}